// round 1
// baseline (speedup 1.0000x reference)
#include <cuda_runtime.h>
#include <cstdint>

#define Bdim 256
#define Udim 512
#define Ddim 512
#define N4U  2048

// ---------------- scratch (no allocations allowed) ----------------
__device__ float g_pre[Bdim * N4U];    // gates pre-activations [B, 4U]
__device__ float g_hw [Bdim * Udim];   // h_tm1 @ w
__device__ float g_red[Bdim * Udim];   // sum_u h[b,u]*hebb[b,u,v]
__device__ float g_g  [Bdim * Udim];   // eta[b,v]*itc[b,v]

// ---------------- tiled fp32 GEMM: 64x64 tile, 4x4 per thread ----------------
// C[m,n] = bias[n] + A1[m,:]@B1[:,n] (+ A2[m,:]@B2[:,n] unless n in c-slice)
// K = 512 fixed. N is the ld of B and C.
template<int N, bool GATES>
__global__ void gemm_tile(const float* __restrict__ A1, const float* __restrict__ B1,
                          const float* __restrict__ A2, const float* __restrict__ B2,
                          const float* __restrict__ bias, float* __restrict__ C)
{
    const int K = 512;
    __shared__ float As[16][64];
    __shared__ float Bs[16][64];

    int tid = threadIdx.x;           // 256 threads
    int tx  = tid & 15;              // 16 col-groups
    int ty  = tid >> 4;              // 16 row-groups
    int m0  = blockIdx.y * 64;
    int n0  = blockIdx.x * 64;

    float acc[4][4];
    #pragma unroll
    for (int p = 0; p < 4; ++p)
        #pragma unroll
        for (int q = 0; q < 4; ++q) acc[p][q] = 0.f;

    bool do_rec = GATES ? !(n0 >= 2 * Udim && n0 < 3 * Udim) : false;
    int npass = GATES ? 2 : 1;

    for (int pass = 0; pass < npass; ++pass) {
        if (pass == 1 && !do_rec) break;
        const float* A = pass ? A2 : A1;   // [256, 512], ld 512
        const float* B = pass ? B2 : B1;   // [512, N],   ld N

        for (int k0 = 0; k0 < K; k0 += 16) {
            #pragma unroll
            for (int t = 0; t < 4; ++t) {
                int i = tid + t * 256;
                int m = i >> 4;
                int k = i & 15;
                As[k][m] = A[(m0 + m) * K + k0 + k];
            }
            #pragma unroll
            for (int t = 0; t < 4; ++t) {
                int i = tid + t * 256;
                int k = i >> 6;
                int n = i & 63;
                Bs[k][n] = B[(k0 + k) * N + n0 + n];
            }
            __syncthreads();
            #pragma unroll
            for (int kk = 0; kk < 16; ++kk) {
                float4 av = *(const float4*)&As[kk][ty * 4];
                float4 bv = *(const float4*)&Bs[kk][tx * 4];
                float a[4] = {av.x, av.y, av.z, av.w};
                float b[4] = {bv.x, bv.y, bv.z, bv.w};
                #pragma unroll
                for (int p = 0; p < 4; ++p)
                    #pragma unroll
                    for (int q = 0; q < 4; ++q)
                        acc[p][q] += a[p] * b[q];
            }
            __syncthreads();
        }
    }

    #pragma unroll
    for (int p = 0; p < 4; ++p) {
        int m = m0 + ty * 4 + p;
        #pragma unroll
        for (int q = 0; q < 4; ++q) {
            int n = n0 + tx * 4 + q;
            float v = acc[p][q];
            if (GATES) v += bias[n];
            C[m * N + n] = v;
        }
    }
}

// ---------------- pass 1 over hebb: red[b,v] = sum_u h[b,u]*hebb[b,u,v] ----------------
__global__ void hebb_reduce(const float* __restrict__ h, const float* __restrict__ hebb,
                            float* __restrict__ red)
{
    int b = blockIdx.y;
    int v = blockIdx.x * 128 + threadIdx.x;

    __shared__ float hs[Udim];
    for (int i = threadIdx.x; i < Udim; i += 128) hs[i] = h[b * Udim + i];
    __syncthreads();

    const float* p = hebb + (size_t)b * Udim * Udim + v;
    float acc0 = 0.f, acc1 = 0.f, acc2 = 0.f, acc3 = 0.f;
    #pragma unroll 2
    for (int u = 0; u < Udim; u += 4) {
        acc0 += hs[u + 0] * p[(size_t)(u + 0) * Udim];
        acc1 += hs[u + 1] * p[(size_t)(u + 1) * Udim];
        acc2 += hs[u + 2] * p[(size_t)(u + 2) * Udim];
        acc3 += hs[u + 3] * p[(size_t)(u + 3) * Udim];
    }
    red[b * Udim + v] = (acc0 + acc1) + (acc2 + acc3);
}

// ---------------- combine: gates, c, h, eta reduction, g ----------------
__device__ __forceinline__ float hsig(float z) {
    return fminf(fmaxf(0.2f * z + 0.5f, 0.f), 1.f);
}

__global__ void combine_kernel(const float* __restrict__ pre, const float* __restrict__ hw,
                               const float* __restrict__ red, const float* __restrict__ c_tm1,
                               const float* __restrict__ alpha, const float* __restrict__ h2mod,
                               const float* __restrict__ fanout,
                               float* __restrict__ out, float* __restrict__ g)
{
    int b = blockIdx.x;
    int v = threadIdx.x;                  // 512 threads

    float xi = pre[b * N4U + v];
    float xf = pre[b * N4U + Udim + v];
    float xc = pre[b * N4U + 2 * Udim + v];
    float xo = pre[b * N4U + 3 * Udim + v];

    float gi = hsig(xi), gf = hsig(xf), go = hsig(xo);
    float itc = tanhf(xc + hw[b * Udim + v] + alpha[v] * red[b * Udim + v]);
    float c = gf * c_tm1[b * Udim + v] + gi * itc;
    float h = go * tanhf(c);

    out[b * Udim + v] = h;                       // h output
    out[Bdim * Udim + b * Udim + v] = c;         // c output

    __shared__ float sdata[Udim];
    sdata[v] = h * h2mod[v];
    __syncthreads();
    #pragma unroll
    for (int s = 256; s > 0; s >>= 1) {
        if (v < s) sdata[v] += sdata[v + s];
        __syncthreads();
    }
    float eta = tanhf(sdata[0]);
    g[b * Udim + v] = eta * fanout[v] * itc;
}

// ---------------- pass 2 over hebb: hebb_new = clip(hebb + h_tm1[b,u]*g[b,v]) ----------------
__global__ void hebb_update(const float* __restrict__ hebb, const float* __restrict__ h_tm1,
                            const float* __restrict__ g, float* __restrict__ out)
{
    int idx = blockIdx.x * 256 + threadIdx.x;   // float4 index, 16,777,216 total
    int row = idx >> 7;                          // (b*512 + u)
    int v4  = idx & 127;
    int b   = row >> 9;

    float hu = h_tm1[row];
    float4 hv = ((const float4*)hebb)[idx];
    float4 gg = ((const float4*)(g + b * Udim))[v4];

    float4 r;
    r.x = fminf(fmaxf(hv.x + hu * gg.x, -2.f), 2.f);
    r.y = fminf(fmaxf(hv.y + hu * gg.y, -2.f), 2.f);
    r.z = fminf(fmaxf(hv.z + hu * gg.z, -2.f), 2.f);
    r.w = fminf(fmaxf(hv.w + hu * gg.w, -2.f), 2.f);
    ((float4*)out)[idx] = r;
}

// ---------------- launch ----------------
extern "C" void kernel_launch(void* const* d_in, const int* in_sizes, int n_in,
                              void* d_out, int out_size)
{
    const float* x      = (const float*)d_in[0];
    const float* h_tm1  = (const float*)d_in[1];
    const float* c_tm1  = (const float*)d_in[2];
    const float* hebb   = (const float*)d_in[3];
    const float* kernel = (const float*)d_in[4];
    const float* rec    = (const float*)d_in[5];
    const float* bias   = (const float*)d_in[6];
    const float* w      = (const float*)d_in[7];
    const float* alpha  = (const float*)d_in[8];
    const float* h2mod  = (const float*)d_in[9];
    const float* fanout = (const float*)d_in[10];
    float* out = (float*)d_out;

    float *pre, *hw, *red, *gg;
    cudaGetSymbolAddress((void**)&pre, g_pre);
    cudaGetSymbolAddress((void**)&hw,  g_hw);
    cudaGetSymbolAddress((void**)&red, g_red);
    cudaGetSymbolAddress((void**)&gg,  g_g);

    // gates: pre = bias + x@kernel + h@rec (c-slice rec skipped)
    gemm_tile<N4U, true><<<dim3(N4U / 64, Bdim / 64), 256>>>(x, kernel, h_tm1, rec, bias, pre);
    // hw = h@w
    gemm_tile<Udim, false><<<dim3(Udim / 64, Bdim / 64), 256>>>(h_tm1, w, nullptr, nullptr, nullptr, hw);
    // pass 1 over hebb
    hebb_reduce<<<dim3(4, Bdim), 128>>>(h_tm1, hebb, red);
    // gates + cell + h + eta + g
    combine_kernel<<<Bdim, Udim>>>(pre, hw, red, c_tm1, alpha, h2mod, fanout, out, gg);
    // pass 2 over hebb -> hebb_new output region
    hebb_update<<<65536, 256>>>(hebb, h_tm1, gg, out + 2 * Bdim * Udim);
}